// round 17
// baseline (speedup 1.0000x reference)
#include <cuda_runtime.h>

// AWBM bucket model, single-pass scan. Split-half smem staging (STS.64 in,
// LDS.128 out, conflict-free), register-resident d[8], direct global stores.
// Cross-block: structural collapse of both chains (S-chain saturation,
// B-chain multiplier underflow). R17:
//  (a) generation-ticket flags (atomicAdd-derived launch generation) remove
//      the k_reset kernel entirely — single-kernel graph.
//  (b) warps >= 1 have warp-prefix affine m == 0.0f exactly (k^256 underflow),
//      so they replay without waiting on the B lookback; warp 0 resolves it
//      post-sync and broadcasts by shuffle, overlapping the L2 RT with the
//      other warps' replay + store.

#define NTH 256
#define EPT 8
#define CHUNK (NTH * EPT)       // 2048
#define MAX_CHUNKS 4096
#define POS_INF __int_as_float(0x7f800000)
#define NEG_INF __int_as_float(0xff800000)
#define FULL 0xffffffffu

__device__ uint4 g_st1[MAX_CHUNKS];   // {gen_flag, a, l, h}
__device__ uint4 g_st2[MAX_CHUNKS];   // {gen_flag, m, c, -}
__device__ unsigned g_ticket;         // monotone launch ticket (never reset)

struct Fn  { float a, l, h; };        // x -> min(max(x+a, l), h)
struct Aff { float m, c; };           // x -> m*x + c

__device__ __forceinline__ Fn fn_id() { Fn f; f.a = 0.f; f.l = NEG_INF; f.h = POS_INF; return f; }
__device__ __forceinline__ Fn fn_comb(Fn p, Fn n) {   // p applied first
    Fn r;
    r.a = p.a + n.a;
    r.l = fmaxf(p.l + n.a, n.l);
    r.h = fminf(fmaxf(p.h + n.a, n.l), n.h);
    return r;
}
__device__ __forceinline__ float fn_apply(Fn f, float x) {
    return fminf(fmaxf(x + f.a, f.l), f.h);
}
__device__ __forceinline__ Aff af_id() { Aff a; a.m = 1.f; a.c = 0.f; return a; }
__device__ __forceinline__ Aff af_comb(Aff p, Aff n) {
    Aff r; r.m = n.m * p.m; r.c = n.m * p.c + n.c; return r;
}

__device__ __forceinline__ uint4 ldv4(const uint4* p) {
    uint4 v;
    asm volatile("ld.volatile.global.v4.b32 {%0,%1,%2,%3}, [%4];"
                 : "=r"(v.x), "=r"(v.y), "=r"(v.z), "=r"(v.w) : "l"(p) : "memory");
    return v;
}
__device__ __forceinline__ void stv4(uint4* p, uint4 v) {
    asm volatile("st.volatile.global.v4.b32 [%0], {%1,%2,%3,%4};"
                 :: "l"(p), "r"(v.x), "r"(v.y), "r"(v.z), "r"(v.w) : "memory");
}

__global__ void __launch_bounds__(NTH)
k_main(const float4* __restrict__ x4, const float2* __restrict__ x2,
       float* __restrict__ out, int T, int NC,
       const float* __restrict__ pbfi, const float* __restrict__ pk,
       const float* __restrict__ psmax) {
    __shared__ __align__(16) float sbuf[CHUNK + 16];
    __shared__ float swa[8], swl[8], swh[8];
    __shared__ float swm[8], swc[8];
    __shared__ float s_Sin;
    __shared__ float s_Bin;
    __shared__ int s_flagB;
    __shared__ unsigned s_want;   // this launch's publish value = gen+1
    float* const sA = sbuf;
    float* const sB = sbuf + CHUNK / 2 + 16;

    const float bfi = pbfi[0], k = pk[0], smax = psmax[0];
    const float ombfi = 1.f - bfi, omk = 1.f - k;
    const float kbfi = k * bfi;
    const float k2 = k * k, k4 = k2 * k2, k8 = k4 * k4;   // m = k^EPT
    const int c = blockIdx.x;
    const int base = c * CHUNK;
    const int nvalid = min(CHUNK, T - base);
    const int tid = threadIdx.x;
    const int lane = tid & 31;
    const int w = tid >> 5;
    const int j0 = tid * EPT;

    // generation ticket: launches are stream-serialized, so each launch's
    // NC atomicAdds form a contiguous range -> gen = ticket/NC is uniform.
    if (tid == 0) {
        unsigned t = atomicAdd(&g_ticket, 1u);
        s_want = t / (unsigned)NC + 1u;
        s_flagB = 0;
    }

    // ---- stage diffs (split-half layout) ----
    if (nvalid == CHUNK) {
        const float4* xp = x4 + (base >> 1);
#pragma unroll
        for (int it = 0; it < CHUNK / 2 / NTH; it++) {
            int i = tid + it * NTH;              // float2-diff index (elems 2i, 2i+1)
            float4 v = xp[i];
            float2 dd; dd.x = v.x - v.y; dd.y = v.z - v.w;
            float* p = (((i & 3) < 2) ? sA : sB) + (i >> 2) * 4 + ((i & 1) << 1);
            *(float2*)p = dd;
        }
    } else {
        for (int e = tid; e < nvalid; e += NTH) {
            float2 v = x2[base + e];
            int q = e >> 3, r = e & 7;
            (((r < 4) ? sA : sB) + q * 4)[r & 3] = v.x - v.y;
        }
        for (int e = nvalid + tid; e < CHUNK; e += NTH) {
            int q = e >> 3, r = e & 7;
            (((r < 4) ? sA : sB) + q * 4)[r & 3] = 0.f;
        }
    }
    __syncthreads();

    const unsigned want = s_want;

    // ---- read my 8 diffs: 2x LDS.128, conflict-free ----
    float d[EPT];
    {
        float4 lo = *(const float4*)(sA + tid * 4);
        float4 hi = *(const float4*)(sB + tid * 4);
        d[0] = lo.x; d[1] = lo.y; d[2] = lo.z; d[3] = lo.w;
        d[4] = hi.x; d[5] = hi.y; d[6] = hi.z; d[7] = hi.w;
    }

    // ---- 1) per-thread clamp composition ----
    Fn f = fn_id();
#pragma unroll
    for (int jj = 0; jj < EPT; jj++) {
        float dd = d[jj];
        f.a += dd;
        f.l = fmaxf(f.l + dd, 0.f);
        f.h = fminf(fmaxf(f.h + dd, 0.f), smax);
    }

    // ---- 2) warp inclusive scan (shuffle) ----
    Fn finc = f;
#pragma unroll
    for (int off = 1; off < 32; off <<= 1) {
        Fn up;
        up.a = __shfl_up_sync(FULL, finc.a, off);
        up.l = __shfl_up_sync(FULL, finc.l, off);
        up.h = __shfl_up_sync(FULL, finc.h, off);
        if (lane >= off) finc = fn_comb(up, finc);
    }
    if (lane == 31) { swa[w] = finc.a; swl[w] = finc.l; swh[w] = finc.h; }
    __syncthreads();

    // ---- 3) warp 0: combine warp aggs, publish aggregate, resolve S_in ----
    if (w == 0) {
        Fn wa = fn_id();
        if (lane < 8) { wa.a = swa[lane]; wa.l = swl[lane]; wa.h = swh[lane]; }
        Fn wsc = wa;
#pragma unroll
        for (int off = 1; off < 8; off <<= 1) {
            Fn up;
            up.a = __shfl_up_sync(FULL, wsc.a, off);
            up.l = __shfl_up_sync(FULL, wsc.l, off);
            up.h = __shfl_up_sync(FULL, wsc.h, off);
            if (lane >= off) wsc = fn_comb(up, wsc);
        }
        if (lane < 8) { swa[lane] = wsc.a; swl[lane] = wsc.l; swh[lane] = wsc.h; }
        if (lane == 7) {   // block aggregate
            uint4 s;
            s.x = want;
            s.y = __float_as_uint(wsc.a); s.z = __float_as_uint(wsc.l); s.w = __float_as_uint(wsc.h);
            stv4(&g_st1[c], s);
        }
        if (lane == 0) {
            float Sin;
            if (c == 0) {
                Sin = 0.5f;                       // S_init
            } else {
                Fn L = fn_id();
                int j = c - 1;
                for (;;) {
                    uint4 st;
                    do { st = ldv4(&g_st1[j]); } while (st.x != want);
                    Fn v;
                    v.a = __uint_as_float(st.y);
                    v.l = __uint_as_float(st.z);
                    v.h = __uint_as_float(st.w);
                    L = fn_comb(v, L);
                    if (L.l >= L.h) { Sin = L.h; break; }
                    if (j == 0)     { Sin = fn_apply(L, 0.5f); break; }
                    j--;
                }
            }
            s_Sin = Sin;
        }
    }
    __syncthreads();

    // ---- 4) per-thread start S; excess into d[]; thread affine c (m = k^8) ----
    float S = s_Sin;
    {
        Fn wex = fn_id();
        if (w > 0) { wex.a = swa[w - 1]; wex.l = swl[w - 1]; wex.h = swh[w - 1]; }
        Fn lex;
        lex.a = __shfl_up_sync(FULL, finc.a, 1);
        lex.l = __shfl_up_sync(FULL, finc.l, 1);
        lex.h = __shfl_up_sync(FULL, finc.h, 1);
        if (lane == 0) lex = fn_id();
        Fn tex = fn_comb(wex, lex);
        S = fn_apply(tex, S);
    }

    float cc = 0.f;
#pragma unroll
    for (int jj = 0; jj < EPT; jj++) {
        float dd = d[jj];
        S = fmaxf(S + dd, 0.f);
        float e = fmaxf(S - smax, 0.f);
        S -= e;
        d[jj] = e;
        cc = fmaf(k, cc, kbfi * e);   // cc' = k*(cc + bfi*e); m-chain = k^8 const
    }
    Aff af; af.m = k8; af.c = cc;

    // ---- 5) warp scan of affines ----
    Aff ainc = af;
#pragma unroll
    for (int off = 1; off < 32; off <<= 1) {
        Aff up;
        up.m = __shfl_up_sync(FULL, ainc.m, off);
        up.c = __shfl_up_sync(FULL, ainc.c, off);
        if (lane >= off) ainc = af_comb(up, ainc);
    }
    if (lane == 31) { swm[w] = ainc.m; swc[w] = ainc.c; }
    __syncthreads();

    // ---- 6) warp 0: combine + publish st2 only (lookback deferred) ----
    if (w == 0) {
        Aff wa = af_id();
        if (lane < 8) { wa.m = swm[lane]; wa.c = swc[lane]; }
        Aff wsc = wa;
#pragma unroll
        for (int off = 1; off < 8; off <<= 1) {
            Aff up;
            up.m = __shfl_up_sync(FULL, wsc.m, off);
            up.c = __shfl_up_sync(FULL, wsc.c, off);
            if (lane >= off) wsc = af_comb(up, wsc);
        }
        if (lane < 8) { swm[lane] = wsc.m; swc[lane] = wsc.c; }
        if (lane == 7) {
            uint4 s;
            s.x = want;
            s.y = __float_as_uint(wsc.m); s.z = __float_as_uint(wsc.c); s.w = 0u;
            stv4(&g_st2[c], s);
        }
    }
    __syncthreads();

    // ---- 7) start B: warp 0 resolves lookback (shuffle broadcast); warps>=1
    //         have warp-prefix m == 0 exactly (k^256 underflow) -> no wait.
    Aff wex = af_id();
    if (w > 0) { wex.m = swm[w - 1]; wex.c = swc[w - 1]; }
    Aff lex;
    lex.m = __shfl_up_sync(FULL, ainc.m, 1);
    lex.c = __shfl_up_sync(FULL, ainc.c, 1);
    if (lane == 0) lex = af_id();
    Aff tex = af_comb(wex, lex);

    float B;
    if (w == 0) {
        float Bin = 0.f;
        if (lane == 0) {
            if (c == 0) {
                Bin = 1.0f;                       // B_init
            } else {
                float prod = 1.f, acc = 0.f;
                int j = c - 1;
                for (;;) {
                    uint4 st;
                    do { st = ldv4(&g_st2[j]); } while (st.x != want);
                    float mj = __uint_as_float(st.y);
                    float Cj = __uint_as_float(st.z);
                    acc += prod * Cj;
                    prod *= mj;
                    if (prod == 0.f) { Bin = acc; break; }
                    if (j == 0)      { Bin = acc + prod * 1.0f; break; }
                    j--;
                }
            }
            s_Bin = Bin;
            __threadfence_block();
            *(volatile int*)&s_flagB = 1;
        }
        __syncwarp();
        Bin = __shfl_sync(FULL, Bin, 0);
        B = tex.m * Bin + tex.c;
    } else {
        if (tex.m != 0.f) {                       // fallback, never taken for k=0.5
            while (*(volatile int*)&s_flagB == 0) {}
            B = tex.m * s_Bin + tex.c;
        } else {
            B = tex.c;
        }
    }

    // ---- exact reference replay into d[] ----
#pragma unroll
    for (int jj = 0; jj < EPT; jj++) {
        float e = d[jj];
        float outflow = ombfi * e;
        B = B + bfi * e;
        float baseflow = omk * B;
        B = B - baseflow;
        d[jj] = outflow + baseflow;
    }

    // ---- 8) direct global store from registers (2x STG.128) ----
    if (j0 + EPT <= nvalid) {
        float4* op = (float4*)(out + base + j0);
        float4 v0, v1;
        v0.x = d[0]; v0.y = d[1]; v0.z = d[2]; v0.w = d[3];
        v1.x = d[4]; v1.y = d[5]; v1.z = d[6]; v1.w = d[7];
        op[0] = v0;
        op[1] = v1;
    } else {
#pragma unroll
        for (int jj = 0; jj < EPT; jj++)
            if (j0 + jj < nvalid) out[base + j0 + jj] = d[jj];
    }
}

extern "C" void kernel_launch(void* const* d_in, const int* in_sizes, int n_in,
                              void* d_out, int out_size) {
    const float4* x4   = (const float4*)d_in[0];
    const float2* x2   = (const float2*)d_in[0];
    const float*  BFI  = (const float*)d_in[1];
    const float*  K    = (const float*)d_in[2];
    const float*  Smax = (const float*)d_in[3];
    float* out = (float*)d_out;

    const int T  = in_sizes[0] / 2;
    const int NC = (T + CHUNK - 1) / CHUNK;   // 3907 for T = 8e6

    k_main<<<NC, NTH>>>(x4, x2, out, T, NC, BFI, K, Smax);
}